// round 14
// baseline (speedup 1.0000x reference)
#include <cuda_runtime.h>

// Problem shape (fixed for this dataset)
#define N_NODES 400000
#define K_DOWN  5
#define NCONTRIB (N_NODES * K_DOWN)   // 2,000,000
#define F_DIM   128
#define NUP     100000
#define CAP     32                    // bucket capacity per destination
#define UPW     4                     // outputs per warp in the gather

// Scratch (allocation-free rule: __device__ globals)
// entry = (w:f32 << 32) | src:u32 ; 400k * 32 * 8B = 102.4 MB
__device__ unsigned long long g_ent[(size_t)N_NODES * CAP];
// counter: high32 = epoch tag, low32 = count. Stale-tagged rows are ignored,
// so no full-array reset is ever needed.
__device__ unsigned long long g_cnt64[N_NODES];
__device__ unsigned int       g_epoch;   // zero-init; bumped once per launch

// ---------------------------------------------------------------------------
// K0: bump the epoch (replaces the 400k-counter clear pass entirely)
__global__ void k_epoch() {
    if (threadIdx.x == 0 && blockIdx.x == 0) g_epoch = g_epoch + 1u;
}

// K1: mark selected destinations: counter -> (epoch<<32 | 0).
__global__ void k_mark(const int* __restrict__ sel) {
    int t = blockIdx.x * blockDim.x + threadIdx.x;
    if (t >= NUP) return;
    int s = sel[t];
    if (s >= 0 && s < N_NODES)
        g_cnt64[s] = ((unsigned long long)g_epoch) << 32;
}

// K2: bucket fill — thread per (n,k) contribution. ONE 64-bit atomic per
// contribution; the slot is accepted only if the counter's epoch tag is
// current (i.e., the destination was marked this launch). ~78% of the
// scattered bucket stores are skipped.
__global__ void k_fill(const float* __restrict__ wdn,
                       const int*   __restrict__ nidx) {
    int t = blockIdx.x * blockDim.x + threadIdx.x;
    if (t >= NCONTRIB) return;
    int dst = nidx[t];
    if (dst < 0 || dst >= N_NODES) return;
    unsigned int ep = g_epoch;
    unsigned long long old = atomicAdd(&g_cnt64[dst], 1ull);
    unsigned int tag = (unsigned int)(old >> 32);
    unsigned int pos = (unsigned int)old;
    if (tag == ep && pos < CAP) {
        float w  = wdn[t];
        int src  = t / K_DOWN;
        unsigned long long e =
            ((unsigned long long)__float_as_uint(w) << 32) | (unsigned int)src;
        g_ent[(size_t)dst * CAP + pos] = e;
    }
}

// K3: fused gather + normalize — FOUR output rows per warp.
//  * one 64-bit load/lane covers slots 0..7 of all four buckets
//  * j-loop unrolled with the 4 outputs interleaved per step
//  * dead slots are PREDICATED OFF (zero-init f, conditional load):
//    no dummy traffic, fewer L1 wavefronts / LSU issue slots
//  * rare tail c > 8 handled serially per output
__global__ void k_gather_fused(const int*   __restrict__ sel,
                               const float* __restrict__ feat,
                               float*       __restrict__ out) {
    int warp = (blockIdx.x * blockDim.x + threadIdx.x) >> 5;
    int u0 = warp * UPW;
    if (u0 >= NUP) return;
    int lane = threadIdx.x & 31;
    int grp  = lane >> 3;          // which of the 4 outputs this lane serves
    int slot = lane & 7;           // bucket slot 0..7

    // uniform scalar loads: all lanes hold all four (s, c)
    int s[UPW], c[UPW];
    #pragma unroll
    for (int i = 0; i < UPW; i++) {
        int u = u0 + i;
        int sv = (u < NUP) ? sel[u] : -1;
        s[i] = (sv >= 0 && sv < N_NODES) ? sv : -1;
    }
    #pragma unroll
    for (int i = 0; i < UPW; i++) {
        // low word = count (tag is guaranteed current for marked rows)
        int cv = (s[i] >= 0) ? (int)(unsigned int)g_cnt64[s[i]] : 0;
        if (cv > CAP) cv = CAP;
        c[i] = cv;
    }

    // one coalesced trip: slots 0..7 of all four buckets
    int sg = s[grp];
    unsigned long long ev = (sg >= 0)
        ? __ldcs(g_ent + (size_t)sg * CAP + slot) : 0ull;

    const float4* feat4 = (const float4*)feat;
    float  wsum[UPW];
    float4 acc [UPW];
    #pragma unroll
    for (int i = 0; i < UPW; i++) {
        wsum[i] = 0.0f;
        acc[i]  = make_float4(0.f, 0.f, 0.f, 0.f);
    }

    #pragma unroll
    for (int j = 0; j < 8; j++) {
        float  wj[UPW];
        float4 f [UPW];
        #pragma unroll
        for (int i = 0; i < UPW; i++) {
            unsigned long long e = __shfl_sync(0xffffffffu, ev, i * 8 + j);
            bool v  = (j < c[i]);
            wj[i]   = v ? __uint_as_float((unsigned int)(e >> 32)) : 0.0f;
            f[i]    = make_float4(0.f, 0.f, 0.f, 0.f);
            if (v) {
                int sj = (int)(unsigned int)(e & 0xffffffffull);
                f[i] = feat4[(size_t)sj * (F_DIM / 4) + lane];
            }
        }
        #pragma unroll
        for (int i = 0; i < UPW; i++) {
            wsum[i] += wj[i];
            acc[i].x = fmaf(wj[i], f[i].x, acc[i].x);
            acc[i].y = fmaf(wj[i], f[i].y, acc[i].y);
            acc[i].z = fmaf(wj[i], f[i].z, acc[i].z);
            acc[i].w = fmaf(wj[i], f[i].w, acc[i].w);
        }
    }

    // rare tail: c > 8 (P ~ 7% per output)
    #pragma unroll
    for (int i = 0; i < UPW; i++) {
        if (c[i] > 8) {
            const unsigned long long* bucket = g_ent + (size_t)s[i] * CAP;
            for (int j = 8; j < c[i]; j++) {
                unsigned long long e = __ldcs(bucket + j);  // uniform broadcast
                int   sj = (int)(unsigned int)(e & 0xffffffffull);
                float w  = __uint_as_float((unsigned int)(e >> 32));
                float4 ft = feat4[(size_t)sj * (F_DIM / 4) + lane];
                wsum[i] += w;
                acc[i].x = fmaf(w, ft.x, acc[i].x);
                acc[i].y = fmaf(w, ft.y, acc[i].y);
                acc[i].z = fmaf(w, ft.z, acc[i].z);
                acc[i].w = fmaf(w, ft.w, acc[i].w);
            }
        }
    }

    // normalize + write
    #pragma unroll
    for (int i = 0; i < UPW; i++) {
        int u = u0 + i;
        if (u >= NUP) break;
        float ws  = (wsum[i] > 0.0f) ? wsum[i] : 0.001f;
        float inv = 1.0f / ws;
        float4 o  = make_float4(acc[i].x * inv, acc[i].y * inv,
                                acc[i].z * inv, acc[i].w * inv);
        __stcs((float4*)(out + (size_t)u * F_DIM) + lane, o);
    }
}

// ---------------------------------------------------------------------------
extern "C" void kernel_launch(void* const* d_in, const int* in_sizes, int n_in,
                              void* d_out, int out_size) {
    const float* feat = (const float*)d_in[0];   // (N, 128) f32
    const float* wdn  = (const float*)d_in[1];   // (N, 5)   f32
    const int*   nidx = (const int*)  d_in[2];   // (N, 5)   i32
    const int*   sel  = (const int*)  d_in[3];   // (NUP, 1) i32
    float* out = (float*)d_out;                  // (NUP, 128) f32

    const int TPB = 256;

    // K0: bump epoch (invalidates all stale counters in O(1))
    k_epoch<<<1, 32>>>();

    // K1: mark selected destinations with the new epoch
    k_mark<<<(NUP + TPB - 1) / TPB, TPB>>>(sel);

    // K2: bucket fill (thread per contribution, selected dsts only)
    k_fill<<<(NCONTRIB + TPB - 1) / TPB, TPB>>>(wdn, nidx);

    // K3: fused gather + normalize (4 output rows per warp)
    {
        int warps  = (NUP + UPW - 1) / UPW;          // 25000
        long long thr = (long long)warps * 32;
        k_gather_fused<<<(int)((thr + TPB - 1) / TPB), TPB>>>(sel, feat, out);
    }
}